// round 5
// baseline (speedup 1.0000x reference)
#include <cuda_runtime.h>
#include <cstdint>
#include <math.h>

// Problem constants
#define BB   4
#define SS_  1024
#define DD   1024
#define HH_  16
#define DK_  64
#define DFF_ 4096
#define TOK  (BB*SS_)          // 4096 tokens

// ---------------------------------------------------------------------------
// Scratch (static __device__ arrays — the sanctioned no-alloc mechanism)
// ---------------------------------------------------------------------------
__device__ float g_nx  [TOK*DD];
__device__ float g_q   [TOK*DD];
__device__ float g_k   [TOK*DD];
__device__ float g_v   [TOK*DD];
__device__ float g_scores[64*1024*1024];   // [B*H][S][S]  256 MB
__device__ float g_ctx [TOK*DD];
__device__ float g_x1  [TOK*DD];
__device__ float g_nx2 [TOK*DD];
__device__ float g_ff  [TOK*DFF_];         // gelu(nx2@w1+b1)  64 MB
__device__ float g_y   [TOK*DD];
__device__ float g_lny [TOK*DD];

#define DEVI __device__ __forceinline__

DEVI float f2tf32(float x) {
    uint32_t u;
    asm("cvt.rna.tf32.f32 %0, %1;" : "=r"(u) : "f"(x));
    return __uint_as_float(u);
}
DEVI float gelu_exact(float x) {
    return 0.5f * x * (1.0f + erff(x * 0.70710678118654752f));
}

enum { EPI_NONE = 0, EPI_BIAS = 1, EPI_BIAS_GELU = 2, EPI_BIAS_RES = 3,
       EPI_BIAS_RES2 = 4, EPI_ATTN = 5 };

// ---------------------------------------------------------------------------
// Generic batched tf32 GEMM:  C = A @ B (+ epilogue)
//   A row-major [M,K] (lda), B row-major [K,N] (ldb) unless BTRANS:
//   BTRANS: logical B[k][n] = Bglob[n*ldb + k]  (used for Q@K^T)
//   batch z: off = (z/HHd)*s1 + (z%HHd)*s2 for A/B/C independently.
//   Tile 128x128x32, 256 threads (8 warps, 4x2), warp tile 32x64,
//   mma.sync.aligned.m16n8k8 tf32.
//   Requires K % 32 == 0, N % 2 == 0 (true for all call sites).
// ---------------------------------------------------------------------------
template <int EPI, bool BTRANS>
__global__ __launch_bounds__(256, 2)
void gemm_tf32_kernel(const float* __restrict__ A, int lda, long long sA1, long long sA2,
                      const float* __restrict__ B, int ldb, long long sB1, long long sB2,
                      float* __restrict__ C, int ldc, long long sC1, long long sC2,
                      int M, int N, int K, int HHd,
                      const float* __restrict__ bias,
                      const float* __restrict__ res1,
                      const float* __restrict__ res2)
{
    __shared__ float As[128][36];   // padded: bank-conflict-free frag loads
    __shared__ float Bs[32][132];

    const int z  = blockIdx.z;
    const int b1 = z / HHd;
    const int b2 = z % HHd;
    A += (size_t)((long long)b1 * sA1 + (long long)b2 * sA2);
    B += (size_t)((long long)b1 * sB1 + (long long)b2 * sB2);
    const size_t coff = (size_t)((long long)b1 * sC1 + (long long)b2 * sC2);

    const int tid  = threadIdx.x;
    const int warp = tid >> 5;
    const int lane = tid & 31;
    const int wm = (warp >> 1) * 32;   // warp row offset in tile: 0/32/64/96
    const int wn = (warp & 1) * 64;    // warp col offset in tile: 0/64
    const int r  = lane >> 2;          // groupID
    const int cq = lane & 3;           // threadID_in_group

    const int blockM = blockIdx.y * 128;
    const int blockN = blockIdx.x * 128;

    float acc[2][8][4];
#pragma unroll
    for (int mt = 0; mt < 2; mt++)
#pragma unroll
        for (int nt = 0; nt < 8; nt++)
#pragma unroll
            for (int i = 0; i < 4; i++) acc[mt][nt][i] = 0.0f;

    for (int k0 = 0; k0 < K; k0 += 32) {
        // ---- stage A tile: 128x32 (4 float4 per thread) ----
#pragma unroll
        for (int i = 0; i < 4; i++) {
            int idx = tid + i * 256;
            int row = idx >> 3;
            int c4  = (idx & 7) * 4;
            int gr  = blockM + row;
            float4 vv = make_float4(0.f, 0.f, 0.f, 0.f);
            if (gr < M)
                vv = *(const float4*)(A + (size_t)gr * lda + (k0 + c4));
            float4 cv = make_float4(f2tf32(vv.x), f2tf32(vv.y), f2tf32(vv.z), f2tf32(vv.w));
            *(float4*)&As[row][c4] = cv;
        }
        // ---- stage B tile: 32x128 ----
        if (!BTRANS) {
#pragma unroll
            for (int i = 0; i < 4; i++) {
                int idx = tid + i * 256;
                int kr  = idx >> 5;
                int c4  = (idx & 31) * 4;
                int gc  = blockN + c4;
                float4 vv = make_float4(0.f, 0.f, 0.f, 0.f);
                if (gc < N)
                    vv = *(const float4*)(B + (size_t)(k0 + kr) * ldb + gc);
                float4 cv = make_float4(f2tf32(vv.x), f2tf32(vv.y), f2tf32(vv.z), f2tf32(vv.w));
                *(float4*)&Bs[kr][c4] = cv;
            }
        } else {
            // B[k][n] = Bglob[n][k]: read contiguous k, transpose into SMEM
#pragma unroll
            for (int i = 0; i < 4; i++) {
                int idx = tid + i * 256;
                int nr  = idx >> 3;          // 0..127 (n)
                int c4  = (idx & 7) * 4;     // 0..28  (k)
                int gc  = blockN + nr;
                float4 vv = make_float4(0.f, 0.f, 0.f, 0.f);
                if (gc < N)
                    vv = *(const float4*)(B + (size_t)gc * ldb + (k0 + c4));
                Bs[c4 + 0][nr] = f2tf32(vv.x);
                Bs[c4 + 1][nr] = f2tf32(vv.y);
                Bs[c4 + 2][nr] = f2tf32(vv.z);
                Bs[c4 + 3][nr] = f2tf32(vv.w);
            }
        }
        __syncthreads();

#pragma unroll
        for (int kk = 0; kk < 32; kk += 8) {
            uint32_t af[2][4];
#pragma unroll
            for (int mt = 0; mt < 2; mt++) {
                int row = wm + mt * 16 + r;
                af[mt][0] = __float_as_uint(As[row    ][kk + cq    ]);
                af[mt][1] = __float_as_uint(As[row + 8][kk + cq    ]);
                af[mt][2] = __float_as_uint(As[row    ][kk + cq + 4]);
                af[mt][3] = __float_as_uint(As[row + 8][kk + cq + 4]);
            }
#pragma unroll
            for (int nt = 0; nt < 8; nt++) {
                uint32_t bf0 = __float_as_uint(Bs[kk + cq    ][wn + nt * 8 + r]);
                uint32_t bf1 = __float_as_uint(Bs[kk + cq + 4][wn + nt * 8 + r]);
#pragma unroll
                for (int mt = 0; mt < 2; mt++) {
                    asm volatile(
                        "mma.sync.aligned.m16n8k8.row.col.f32.tf32.tf32.f32 "
                        "{%0,%1,%2,%3}, {%4,%5,%6,%7}, {%8,%9}, {%0,%1,%2,%3};"
                        : "+f"(acc[mt][nt][0]), "+f"(acc[mt][nt][1]),
                          "+f"(acc[mt][nt][2]), "+f"(acc[mt][nt][3])
                        : "r"(af[mt][0]), "r"(af[mt][1]), "r"(af[mt][2]), "r"(af[mt][3]),
                          "r"(bf0), "r"(bf1));
                }
            }
        }
        __syncthreads();
    }

    // ---- epilogue + store ----
    float* Cb = C + coff;
#pragma unroll
    for (int mt = 0; mt < 2; mt++) {
#pragma unroll
        for (int nt = 0; nt < 8; nt++) {
#pragma unroll
            for (int rh = 0; rh < 2; rh++) {
                int grow = blockM + wm + mt * 16 + r + rh * 8;
                int gcol = blockN + wn + nt * 8 + cq * 2;
                if (grow < M && gcol < N) {
                    float v0 = acc[mt][nt][rh * 2 + 0];
                    float v1 = acc[mt][nt][rh * 2 + 1];
                    size_t cidx = (size_t)grow * ldc + gcol;
                    if (EPI == EPI_ATTN) {
                        // scores/8 + rel_table[clip(t - s + 63, 0, 126)][h]
                        int d0 = gcol     - grow + 63; d0 = min(max(d0, 0), 126);
                        int d1 = gcol + 1 - grow + 63; d1 = min(max(d1, 0), 126);
                        v0 = v0 * 0.125f + bias[d0 * HH_ + b2];
                        v1 = v1 * 0.125f + bias[d1 * HH_ + b2];
                    } else if (EPI != EPI_NONE) {
                        v0 += bias[gcol];
                        v1 += bias[gcol + 1];
                    }
                    if (EPI == EPI_BIAS_GELU) { v0 = gelu_exact(v0); v1 = gelu_exact(v1); }
                    if (EPI == EPI_BIAS_RES || EPI == EPI_BIAS_RES2) {
                        v0 += res1[cidx]; v1 += res1[cidx + 1];
                    }
                    if (EPI == EPI_BIAS_RES2) {
                        v0 += res2[cidx]; v1 += res2[cidx + 1];
                    }
                    *(float2*)(Cb + cidx) = make_float2(v0, v1);
                }
            }
        }
    }
}

// ---------------------------------------------------------------------------
// LayerNorm: one 1024-wide row per block of 256 threads
// ---------------------------------------------------------------------------
__global__ void ln_kernel(const float* __restrict__ x, const float* __restrict__ g,
                          const float* __restrict__ b, float* __restrict__ out)
{
    __shared__ float sb[8];
    const int row = blockIdx.x;
    const int t   = threadIdx.x;
    float4 v = ((const float4*)(x + (size_t)row * DD))[t];

    float s = v.x + v.y + v.z + v.w;
#pragma unroll
    for (int o = 16; o; o >>= 1) s += __shfl_xor_sync(0xffffffffu, s, o);
    if ((t & 31) == 0) sb[t >> 5] = s;
    __syncthreads();
    float mean = (sb[0]+sb[1]+sb[2]+sb[3]+sb[4]+sb[5]+sb[6]+sb[7]) * (1.0f / DD);
    __syncthreads();

    float d0 = v.x - mean, d1 = v.y - mean, d2 = v.z - mean, d3 = v.w - mean;
    float s2 = d0*d0 + d1*d1 + d2*d2 + d3*d3;
#pragma unroll
    for (int o = 16; o; o >>= 1) s2 += __shfl_xor_sync(0xffffffffu, s2, o);
    if ((t & 31) == 0) sb[t >> 5] = s2;
    __syncthreads();
    float var = (sb[0]+sb[1]+sb[2]+sb[3]+sb[4]+sb[5]+sb[6]+sb[7]) * (1.0f / DD);
    float inv = rsqrtf(var + 1e-5f);

    float4 gv = ((const float4*)g)[t];
    float4 bv = ((const float4*)b)[t];
    float4 o4 = make_float4(d0 * inv * gv.x + bv.x, d1 * inv * gv.y + bv.y,
                            d2 * inv * gv.z + bv.z, d3 * inv * gv.w + bv.w);
    ((float4*)(out + (size_t)row * DD))[t] = o4;
}

// ---------------------------------------------------------------------------
// Row softmax over 1024 elems, in place. One row per block of 256 threads.
// ---------------------------------------------------------------------------
__global__ void softmax_kernel(float* __restrict__ scores)
{
    __shared__ float sb[8];
    const size_t row = blockIdx.x;
    const int t = threadIdx.x;
    float4* p = (float4*)(scores + row * 1024);
    float4 v = p[t];

    float m = fmaxf(fmaxf(v.x, v.y), fmaxf(v.z, v.w));
#pragma unroll
    for (int o = 16; o; o >>= 1) m = fmaxf(m, __shfl_xor_sync(0xffffffffu, m, o));
    if ((t & 31) == 0) sb[t >> 5] = m;
    __syncthreads();
    m = fmaxf(fmaxf(fmaxf(sb[0], sb[1]), fmaxf(sb[2], sb[3])),
              fmaxf(fmaxf(sb[4], sb[5]), fmaxf(sb[6], sb[7])));
    __syncthreads();

    float e0 = __expf(v.x - m), e1 = __expf(v.y - m);
    float e2 = __expf(v.z - m), e3 = __expf(v.w - m);
    float s = e0 + e1 + e2 + e3;
#pragma unroll
    for (int o = 16; o; o >>= 1) s += __shfl_xor_sync(0xffffffffu, s, o);
    if ((t & 31) == 0) sb[t >> 5] = s;
    __syncthreads();
    float tot = sb[0]+sb[1]+sb[2]+sb[3]+sb[4]+sb[5]+sb[6]+sb[7];
    float inv = 1.0f / tot;
    p[t] = make_float4(e0 * inv, e1 * inv, e2 * inv, e3 * inv);
}

// ---------------------------------------------------------------------------
// Launch
// ---------------------------------------------------------------------------
extern "C" void kernel_launch(void* const* d_in, const int* in_sizes, int n_in,
                              void* d_out, int out_size)
{
    (void)in_sizes; (void)n_in; (void)out_size;
    const float* x    = (const float*)d_in[0];
    const float* wq   = (const float*)d_in[1];
    const float* bq   = (const float*)d_in[2];
    const float* wk   = (const float*)d_in[3];
    const float* bk   = (const float*)d_in[4];
    const float* wv   = (const float*)d_in[5];
    const float* bv   = (const float*)d_in[6];
    const float* wo   = (const float*)d_in[7];
    const float* bo   = (const float*)d_in[8];
    const float* relt = (const float*)d_in[9];
    const float* g1   = (const float*)d_in[10];
    const float* be1  = (const float*)d_in[11];
    const float* g2   = (const float*)d_in[12];
    const float* be2  = (const float*)d_in[13];
    const float* w1   = (const float*)d_in[14];
    const float* b1   = (const float*)d_in[15];
    const float* w2   = (const float*)d_in[16];
    const float* b2   = (const float*)d_in[17];
    const float* w3   = (const float*)d_in[18];
    const float* b3   = (const float*)d_in[19];
    const float* gf   = (const float*)d_in[20];
    const float* bf   = (const float*)d_in[21];
    float* out = (float*)d_out;

    float *nx, *q, *k, *v, *sc, *ctx, *x1, *nx2, *ff, *y, *lny;
    cudaGetSymbolAddress((void**)&nx,  g_nx);
    cudaGetSymbolAddress((void**)&q,   g_q);
    cudaGetSymbolAddress((void**)&k,   g_k);
    cudaGetSymbolAddress((void**)&v,   g_v);
    cudaGetSymbolAddress((void**)&sc,  g_scores);
    cudaGetSymbolAddress((void**)&ctx, g_ctx);
    cudaGetSymbolAddress((void**)&x1,  g_x1);
    cudaGetSymbolAddress((void**)&nx2, g_nx2);
    cudaGetSymbolAddress((void**)&ff,  g_ff);
    cudaGetSymbolAddress((void**)&y,   g_y);
    cudaGetSymbolAddress((void**)&lny, g_lny);

    const long long SD = (long long)SS_ * DD;       // 1,048,576
    const long long S2 = (long long)SS_ * SS_;      // 1,048,576

    // 1. nx = LN(x, g1, be1)
    ln_kernel<<<TOK, 256>>>(x, g1, be1, nx);

    // 2-4. Q/K/V = nx @ w + b   [4096,1024]
    gemm_tf32_kernel<EPI_BIAS, false><<<dim3(8, 32, 1), 256>>>(
        nx, DD, 0, 0, wq, DD, 0, 0, q, DD, 0, 0, TOK, DD, DD, 1, bq, nullptr, nullptr);
    gemm_tf32_kernel<EPI_BIAS, false><<<dim3(8, 32, 1), 256>>>(
        nx, DD, 0, 0, wk, DD, 0, 0, k, DD, 0, 0, TOK, DD, DD, 1, bk, nullptr, nullptr);
    gemm_tf32_kernel<EPI_BIAS, false><<<dim3(8, 32, 1), 256>>>(
        nx, DD, 0, 0, wv, DD, 0, 0, v, DD, 0, 0, TOK, DD, DD, 1, bv, nullptr, nullptr);

    // 5. scores[bh] = Q_bh @ K_bh^T / 8 + rel_bias   (batched, BTRANS)
    gemm_tf32_kernel<EPI_ATTN, true><<<dim3(8, 8, BB * HH_), 256>>>(
        q, DD, SD, DK_, k, DD, SD, DK_, sc, SS_, (long long)HH_ * S2, S2,
        SS_, SS_, DK_, HH_, relt, nullptr, nullptr);

    // 6. softmax rows
    softmax_kernel<<<BB * HH_ * SS_, 256>>>(sc);

    // 7. ctx[bh] = P @ V_bh   [1024,64] per batch, written head-interleaved
    gemm_tf32_kernel<EPI_NONE, false><<<dim3(1, 8, BB * HH_), 256>>>(
        sc, SS_, (long long)HH_ * S2, S2, v, DD, SD, DK_, ctx, DD, SD, DK_,
        SS_, DK_, SS_, HH_, nullptr, nullptr, nullptr);

    // 8. x1 = x + ctx @ wo + bo
    gemm_tf32_kernel<EPI_BIAS_RES, false><<<dim3(8, 32, 1), 256>>>(
        ctx, DD, 0, 0, wo, DD, 0, 0, x1, DD, 0, 0, TOK, DD, DD, 1, bo, x, nullptr);

    // 9. nx2 = LN(x1)
    ln_kernel<<<TOK, 256>>>(x1, g2, be2, nx2);

    // 10. ff = gelu(nx2 @ w1 + b1)   [4096,4096]
    gemm_tf32_kernel<EPI_BIAS_GELU, false><<<dim3(32, 32, 1), 256>>>(
        nx2, DD, 0, 0, w1, DFF_, 0, 0, ff, DFF_, 0, 0, TOK, DFF_, DD, 1, b1, nullptr, nullptr);

    // 11. y = nx2 + ff @ w2 + b2
    gemm_tf32_kernel<EPI_BIAS_RES, false><<<dim3(8, 32, 1), 256>>>(
        ff, DFF_, 0, 0, w2, DD, 0, 0, y, DD, 0, 0, TOK, DD, DFF_, 1, b2, nx2, nullptr);

    // 12. lny = LN(y)
    ln_kernel<<<TOK, 256>>>(y, gf, bf, lny);

    // 13. out = x1 + y + lny @ w3 + b3
    gemm_tf32_kernel<EPI_BIAS_RES2, false><<<dim3(8, 32, 1), 256>>>(
        lny, DD, 0, 0, w3, DD, 0, 0, out, DD, 0, 0, TOK, DD, DD, 1, b3, y, x1);
}